// round 10
// baseline (speedup 1.0000x reference)
#include <cuda_runtime.h>

#define N_NODES 100000
#define N_EDGES 3200000
#define F_IN    512
#define NH      16
#define NC      3

// ---------------- scratch (device globals; device-code references ONLY) -----
__device__ int   g_deg_out[N_NODES];
__device__ int   g_deg_in [N_NODES];
__device__ float g_norm_src[N_NODES];
__device__ float g_norm_dst[N_NODES];
__device__ int2  g_edge[N_EDGES];                 // packed (src,dst) int32
__device__ float g_h1  [(size_t)N_NODES * NH];    // feat@W1 (unscaled)
__device__ float g_agg1[(size_t)N_NODES * NH];
__device__ float g_y   [(size_t)N_NODES * 4];     // (relu(agg1*nd+b1)*ns)@W2f
__device__ float g_agg2[(size_t)N_NODES * 4];
__device__ float g_W2f [NH * NC];                 // W2 @ Wfc
__device__ float g_b2f [NC];                      // b2 @ Wfc + bfc
__device__ int   g_idx64;                         // 1 if indices are int64

// ---------------- index dtype detection (int64 vs int32) --------------------
__global__ void k_detect(const int* __restrict__ src_as_i32) {
    int any = 0;
    #pragma unroll
    for (int j = 0; j < 64; j++) any |= src_as_i32[2 * j + 1];
    g_idx64 = (any == 0) ? 1 : 0;
}

__device__ __forceinline__ int load_idx(const void* p, int i, int is64) {
    return is64 ? (int)((const long long*)p)[i] : ((const int*)p)[i];
}

// ---------------- zero accumulators (side stream) ----------------------------
__global__ void k_zero() {
    int i = blockIdx.x * blockDim.x + threadIdx.x;
    if (i < N_NODES * NH) g_agg1[i] = 0.f;
    if (i < N_NODES * 4)  g_agg2[i] = 0.f;
    if (i < N_NODES) { g_deg_out[i] = 0; g_deg_in[i] = 0; }
}

// ---------------- degree histogram + edge compaction (side stream) -----------
__global__ __launch_bounds__(256)
void k_deg(const void* __restrict__ src, const void* __restrict__ dst) {
    int is64 = g_idx64;
    int stride = gridDim.x * blockDim.x;
    for (int i = blockIdx.x * blockDim.x + threadIdx.x; i < N_EDGES; i += stride) {
        int s = load_idx(src, i, is64);
        int d = load_idx(dst, i, is64);
        g_edge[i] = make_int2(s, d);
        asm volatile("red.global.add.u32 [%0], %1;"
                     :: "l"(g_deg_out + s), "r"(1) : "memory");
        asm volatile("red.global.add.u32 [%0], %1;"
                     :: "l"(g_deg_in + d), "r"(1) : "memory");
    }
}

// ---------------- norms (side stream, after k_deg) ---------------------------
__global__ void k_norm() {
    int n = blockIdx.x * blockDim.x + threadIdx.x;
    if (n >= N_NODES) return;
    g_norm_src[n] = rsqrtf(fmaxf((float)g_deg_out[n], 1.f));
    g_norm_dst[n] = rsqrtf(fmaxf((float)g_deg_in [n], 1.f));
}

// ---------------- GEMM1: h1 = feat @ W1, cp.async double-buffered ------------
#define GB 128
#define KC 64
#define NCHUNK (F_IN / KC)                            // 8
#define SF_STRIDE (KC + 4)                            // 68 floats per node row
#define SF_ELEMS  (GB * SF_STRIDE)
#define SMEM_GEMM ((F_IN * NH + 2 * SF_ELEMS) * 4)    // 100 KB

__device__ __forceinline__ void stage_chunk(const float* __restrict__ feat,
                                            float* sF, int n0, int c, int tid) {
    #pragma unroll
    for (int t = tid; t < GB * (KC / 4); t += 256) {
        int node = t >> 4;                            // KC/4 == 16
        int q    = t & 15;
        int n    = n0 + node;
        const float* gsrc = feat +
            ((size_t)(n < N_NODES ? n : N_NODES - 1) * F_IN + c * KC + q * 4);
        int sz = (n < N_NODES) ? 16 : 0;              // 0 => zero-fill
        unsigned sa = (unsigned)__cvta_generic_to_shared(&sF[node * SF_STRIDE + q * 4]);
        asm volatile("cp.async.cg.shared.global [%0], [%1], 16, %2;"
                     :: "r"(sa), "l"(gsrc), "r"(sz) : "memory");
    }
    asm volatile("cp.async.commit_group;" ::: "memory");
}

__global__ __launch_bounds__(256, 2)
void k_gemm1(const float* __restrict__ feat, const float* __restrict__ W1) {
    extern __shared__ float smem[];
    float* sW  = smem;                                // [512][16]
    float* sF0 = smem + F_IN * NH;                    // 2 x [128][68]

    const int tid = threadIdx.x;
    const int nl  = tid >> 1;                         // local node 0..127
    const int oh  = tid & 1;                          // output half
    const int n0  = blockIdx.x * GB;

    {
        const float4* W4 = (const float4*)W1;
        float4* sW4 = (float4*)sW;
        #pragma unroll
        for (int t = tid; t < F_IN * NH / 4; t += 256) sW4[t] = W4[t];
    }

    stage_chunk(feat, sF0, n0, 0, tid);

    unsigned long long A0 = 0ull, A1 = 0ull, A2 = 0ull, A3 = 0ull;

    for (int c = 0; c < NCHUNK; c++) {
        if (c + 1 < NCHUNK) {
            stage_chunk(feat, sF0 + ((c + 1) & 1) * SF_ELEMS, n0, c + 1, tid);
            asm volatile("cp.async.wait_group 1;" ::: "memory");
        } else {
            asm volatile("cp.async.wait_group 0;" ::: "memory");
        }
        __syncthreads();

        const float* frow = sF0 + (c & 1) * SF_ELEMS + nl * SF_STRIDE;
        const float* wbase = sW + (size_t)c * KC * NH + oh * 8;
        #pragma unroll 4
        for (int kk = 0; kk < KC; kk++) {
            float f = frow[kk];
            unsigned long long fp;
            asm("mov.b64 %0, {%1, %1};" : "=l"(fp) : "f"(f));
            const float* wp = wbase + kk * NH;
            ulonglong2 wa = *(const ulonglong2*)wp;
            ulonglong2 wb = *(const ulonglong2*)(wp + 4);
            asm("fma.rn.f32x2 %0, %1, %2, %0;" : "+l"(A0) : "l"(fp), "l"(wa.x));
            asm("fma.rn.f32x2 %0, %1, %2, %0;" : "+l"(A1) : "l"(fp), "l"(wa.y));
            asm("fma.rn.f32x2 %0, %1, %2, %0;" : "+l"(A2) : "l"(fp), "l"(wb.x));
            asm("fma.rn.f32x2 %0, %1, %2, %0;" : "+l"(A3) : "l"(fp), "l"(wb.y));
        }
        __syncthreads();
    }

    int n = n0 + nl;
    if (n < N_NODES) {
        float2 v0 = *(float2*)&A0, v1 = *(float2*)&A1;
        float2 v2 = *(float2*)&A2, v3 = *(float2*)&A3;
        float4* dst4 = (float4*)&g_h1[(size_t)n * NH + oh * 8];
        dst4[0] = make_float4(v0.x, v0.y, v1.x, v1.y);
        dst4[1] = make_float4(v2.x, v2.y, v3.x, v3.y);
    }
}

// ---------------- edge pass 1: agg1[d] += ns[s]*h1[s]  (4x RED.128) ----------
__device__ __forceinline__ void red4(float* p, float4 v) {
    asm volatile("red.global.add.v4.f32 [%0], {%1,%2,%3,%4};"
                 :: "l"(p), "f"(v.x), "f"(v.y), "f"(v.z), "f"(v.w) : "memory");
}

__global__ void k_edge1() {
    int i = blockIdx.x * blockDim.x + threadIdx.x;
    if (i >= N_EDGES) return;
    int2 e = __ldg(&g_edge[i]);
    float ns = __ldg(&g_norm_src[e.x]);
    const float4* t4 = (const float4*)(g_h1 + (size_t)e.x * NH);
    float4 v0 = __ldg(t4 + 0), v1 = __ldg(t4 + 1);
    float4 v2 = __ldg(t4 + 2), v3 = __ldg(t4 + 3);
    v0.x *= ns; v0.y *= ns; v0.z *= ns; v0.w *= ns;
    v1.x *= ns; v1.y *= ns; v1.z *= ns; v1.w *= ns;
    v2.x *= ns; v2.y *= ns; v2.z *= ns; v2.w *= ns;
    v3.x *= ns; v3.y *= ns; v3.z *= ns; v3.w *= ns;
    float* base = g_agg1 + (size_t)e.y * NH;
    red4(base + 0,  v0);
    red4(base + 4,  v1);
    red4(base + 8,  v2);
    red4(base + 12, v3);
}

// ---------------- W2f = W2 @ Wfc, b2f = b2 @ Wfc + bfc  (warp-parallel) ------
__global__ void k_w2f(const float* __restrict__ W2, const float* __restrict__ b2,
                      const float* __restrict__ Wfc, const float* __restrict__ bfc) {
    int w    = (blockIdx.x * blockDim.x + threadIdx.x) >> 5;
    int lane = threadIdx.x & 31;
    if (w < NH * NC) {
        int h = w / NC, c = w % NC;
        float s = 0.f;
        #pragma unroll
        for (int k = lane; k < 128; k += 32)
            s = fmaf(__ldg(W2 + h * 128 + k), __ldg(Wfc + k * NC + c), s);
        #pragma unroll
        for (int m = 16; m; m >>= 1) s += __shfl_xor_sync(0xffffffffu, s, m);
        if (lane == 0) g_W2f[w] = s;
    } else if (w < NH * NC + NC) {
        int c = w - NH * NC;
        float s = 0.f;
        #pragma unroll
        for (int k = lane; k < 128; k += 32)
            s = fmaf(__ldg(b2 + k), __ldg(Wfc + k * NC + c), s);
        #pragma unroll
        for (int m = 16; m; m >>= 1) s += __shfl_xor_sync(0xffffffffu, s, m);
        if (lane == 0) g_b2f[c] = s + __ldg(bfc + c);
    }
}

// ---------------- y = (relu(agg1*nd+b1)*ns) @ W2f  -> float4 (w=0) -----------
__global__ void k_y(const float* __restrict__ b1) {
    __shared__ float sw[NH * NC];
    if (threadIdx.x < NH * NC) sw[threadIdx.x] = g_W2f[threadIdx.x];
    __syncthreads();
    int n = blockIdx.x * blockDim.x + threadIdx.x;
    if (n >= N_NODES) return;
    const float4* a4 = (const float4*)(g_agg1 + (size_t)n * NH);
    float4 A[4] = {a4[0], a4[1], a4[2], a4[3]};
    const float* af = (const float*)A;
    float nd = g_norm_dst[n];
    float ns = g_norm_src[n];
    float s0 = 0.f, s1 = 0.f, s2 = 0.f;
    #pragma unroll
    for (int h = 0; h < NH; h++) {
        float x = fmaxf(fmaf(af[h], nd, __ldg(b1 + h)), 0.f) * ns;
        s0 = fmaf(x, sw[h * 3 + 0], s0);
        s1 = fmaf(x, sw[h * 3 + 1], s1);
        s2 = fmaf(x, sw[h * 3 + 2], s2);
    }
    ((float4*)g_y)[n] = make_float4(s0, s1, s2, 0.f);
}

// ---------------- edge pass 2: agg2[d] += y[s]  (1x RED.128) -----------------
__global__ void k_edge2() {
    int i = blockIdx.x * blockDim.x + threadIdx.x;
    if (i >= N_EDGES) return;
    int2 e = __ldg(&g_edge[i]);
    float4 v = __ldg((const float4*)g_y + e.x);
    red4(g_agg2 + (size_t)e.y * 4, v);
}

// ---------------- out = nd * agg2.xyz + b2f ----------------------------------
__global__ void k_out(float* __restrict__ out) {
    int n = blockIdx.x * blockDim.x + threadIdx.x;
    if (n >= N_NODES) return;
    float4 a = ((const float4*)g_agg2)[n];
    float nd = g_norm_dst[n];
    out[(size_t)n * 3 + 0] = fmaf(nd, a.x, g_b2f[0]);
    out[(size_t)n * 3 + 1] = fmaf(nd, a.y, g_b2f[1]);
    out[(size_t)n * 3 + 2] = fmaf(nd, a.z, g_b2f[2]);
}

// ---------------- launch ------------------------------------------------------
extern "C" void kernel_launch(void* const* d_in, const int* in_sizes, int n_in,
                              void* d_out, int out_size) {
    const float* feat = (const float*)d_in[0];
    const void*  src  = d_in[1];
    const void*  dst  = d_in[2];
    const float* W1   = (const float*)d_in[3];
    const float* b1   = (const float*)d_in[4];
    const float* W2   = (const float*)d_in[5];
    const float* b2   = (const float*)d_in[6];
    const float* Wfc  = (const float*)d_in[7];
    const float* bfc  = (const float*)d_in[8];
    float* out = (float*)d_out;

    static cudaStream_t s1 = nullptr;
    static cudaEvent_t  e0 = nullptr, e1 = nullptr;
    if (!s1) {
        cudaStreamCreateWithFlags(&s1, cudaStreamNonBlocking);
        cudaEventCreateWithFlags(&e0, cudaEventDisableTiming);
        cudaEventCreateWithFlags(&e1, cudaEventDisableTiming);
        cudaFuncSetAttribute(k_gemm1, cudaFuncAttributeMaxDynamicSharedMemorySize,
                             SMEM_GEMM);
    }

    const int EB = (N_EDGES + 255) / 256;            // 12500
    const int NB = (N_NODES + 255) / 256;            // 391

    // main stream: detect -> (fork) -> gemm1 (long)
    k_detect<<<1, 1>>>((const int*)src);
    cudaEventRecord(e0, 0);

    // side stream: zero + deg/pack + norms + W2f, overlapped with gemm1
    cudaStreamWaitEvent(s1, e0, 0);
    k_zero<<<(N_NODES * NH + 255) / 256, 256, 0, s1>>>();
    k_deg <<<2048, 256, 0, s1>>>(src, dst);
    k_norm<<<NB, 256, 0, s1>>>();
    k_w2f <<<2, 1024, 0, s1>>>(W2, b2, Wfc, bfc);
    cudaEventRecord(e1, s1);

    // main stream continues
    k_gemm1<<<(N_NODES + GB - 1) / GB, 256, SMEM_GEMM>>>(feat, W1);
    cudaStreamWaitEvent(0, e1, 0);
    k_edge1<<<EB, 256>>>();
    k_y    <<<NB, 256>>>(b1);
    k_edge2<<<EB, 256>>>();
    k_out  <<<NB, 256>>>(out);
}